// round 6
// baseline (speedup 1.0000x reference)
#include <cuda_runtime.h>
#include <cstdint>
#include <math.h>

#define T_TOK 2048
#define DDIM  1024
#define NEXP  64
#define TOPK  8
#define FDIM  768
#define CAP   512

// -------------------- device scratch --------------------
__device__ int   g_cnt[NEXP];
__device__ int   g_slot_tok[NEXP * CAP];
__device__ float g_slot_w[NEXP * CAP];
__device__ float g_H[(size_t)NEXP * CAP * FDIM];        // ~100.7 MB
__device__ float g_shared_h[(size_t)T_TOK * FDIM];      // ~6.3 MB

// -------------------- helpers --------------------
__device__ __forceinline__ uint32_t f2tf32(float x) {
    uint32_t r;
    asm("cvt.rna.tf32.f32 %0, %1;" : "=r"(r) : "f"(x));
    return r;
}

__device__ __forceinline__ void cvt_store4(float* dst, const float* src) {
    float4 v = *reinterpret_cast<const float4*>(src);
    uint4 o;
    o.x = f2tf32(v.x); o.y = f2tf32(v.y); o.z = f2tf32(v.z); o.w = f2tf32(v.w);
    *reinterpret_cast<uint4*>(dst) = o;
}

__device__ __forceinline__ void mma8(float c[4], const uint32_t a[4],
                                     uint32_t b0, uint32_t b1) {
    asm volatile(
        "mma.sync.aligned.m16n8k8.row.col.f32.tf32.tf32.f32 "
        "{%0,%1,%2,%3},{%4,%5,%6,%7},{%8,%9},{%0,%1,%2,%3};\n"
        : "+f"(c[0]), "+f"(c[1]), "+f"(c[2]), "+f"(c[3])
        : "r"(a[0]), "r"(a[1]), "r"(a[2]), "r"(a[3]), "r"(b0), "r"(b1));
}

// -------------------- counters reset --------------------
__global__ void zero_cnt_kernel() {
    if (threadIdx.x < NEXP) g_cnt[threadIdx.x] = 0;
}

// -------------------- router --------------------
// 256 threads, 32 tokens/block. Thread owns token t=tid>>3, experts el+8j.
__global__ __launch_bounds__(256)
void router_kernel(const float* __restrict__ X, const float* __restrict__ RW) {
    __shared__ float xs[32][68];
    __shared__ float rws[64][68];
    __shared__ float probs[32][65];

    const int tid = threadIdx.x;
    const int t0  = blockIdx.x * 32;
    const int t   = tid >> 3;
    const int el  = tid & 7;

    float acc[8] = {0.f,0.f,0.f,0.f,0.f,0.f,0.f,0.f};

    for (int kc = 0; kc < DDIM; kc += 64) {
        #pragma unroll
        for (int i = 0; i < 2; i++) {
            int idx = tid + i * 256;          // 0..511 -> 32 rows x 16 float4
            int row = idx >> 4, c4 = idx & 15;
            *reinterpret_cast<float4*>(&xs[row][c4 * 4]) =
                *reinterpret_cast<const float4*>(X + (size_t)(t0 + row) * DDIM + kc + c4 * 4);
        }
        #pragma unroll
        for (int i = 0; i < 4; i++) {
            int idx = tid + i * 256;          // 0..1023 -> 64 rows x 16 float4
            int row = idx >> 4, c4 = idx & 15;
            *reinterpret_cast<float4*>(&rws[row][c4 * 4]) =
                *reinterpret_cast<const float4*>(RW + (size_t)row * DDIM + kc + c4 * 4);
        }
        __syncthreads();
        for (int k = 0; k < 64; k++) {
            float xv = xs[t][k];
            #pragma unroll
            for (int j = 0; j < 8; j++) acc[j] += xv * rws[el + 8 * j][k];
        }
        __syncthreads();
    }

    // softmax over 64 experts (reduce across this token's 8 lanes)
    float mx = acc[0];
    #pragma unroll
    for (int j = 1; j < 8; j++) mx = fmaxf(mx, acc[j]);
    #pragma unroll
    for (int m = 1; m < 8; m <<= 1) mx = fmaxf(mx, __shfl_xor_sync(0xffffffffu, mx, m));
    float p[8], s = 0.f;
    #pragma unroll
    for (int j = 0; j < 8; j++) { p[j] = expf(acc[j] - mx); s += p[j]; }
    #pragma unroll
    for (int m = 1; m < 8; m <<= 1) s += __shfl_xor_sync(0xffffffffu, s, m);
    float inv = 1.f / s;
    #pragma unroll
    for (int j = 0; j < 8; j++) probs[t][el + 8 * j] = p[j] * inv;
    __syncthreads();

    if (tid < 32) {
        const int token = t0 + tid;
        float tw[TOPK]; int te[TOPK];
        float psum = 0.f;
        #pragma unroll
        for (int k = 0; k < TOPK; k++) {
            float best = -1.f; int be = 0;
            for (int e2 = 0; e2 < NEXP; e2++) {
                float v = probs[tid][e2];
                if (v > best) { best = v; be = e2; }
            }
            probs[tid][be] = -2.f;
            tw[k] = best; te[k] = be; psum += best;
        }
        float invp = 1.f / psum;
        #pragma unroll
        for (int k = 0; k < TOPK; k++) {
            int pos = atomicAdd(&g_cnt[te[k]], 1);
            if (pos < CAP) {
                g_slot_tok[te[k] * CAP + pos] = token;
                g_slot_w[te[k] * CAP + pos]   = tw[k] * invp;
            }
        }
    }
}

// -------------------- fused gate/up GEMM + SiLU --------------------
// BM=128, BN=128, BK=32, 512 threads (16 warps 4x4, 32x32 warp tile).
// per buffer floats: A 128*36=4608, Bg 32*136=4352, Bu 4352 => 13312
template<bool EXPERT>
__global__ __launch_bounds__(512)
void gateup_kernel(const float* __restrict__ X, const float* __restrict__ WG,
                   const float* __restrict__ WU, int ldb) {
    extern __shared__ float smem[];
    float* bufs = smem;
    int* s_tok = (int*)(smem + 2 * 13312);

    const int tid = threadIdx.x;
    const int e  = EXPERT ? blockIdx.z : 0;
    const int ne = EXPERT ? min(g_cnt[e], CAP) : T_TOK;
    const int m0 = blockIdx.y * 128;
    if (m0 >= ne) return;
    const int n0 = blockIdx.x * 128;

    const float* Bg = EXPERT ? (WG + (size_t)e * DDIM * FDIM) : WG;
    const float* Bu = EXPERT ? (WU + (size_t)e * DDIM * FDIM) : WU;

    if (EXPERT) {
        for (int i = tid; i < 128; i += 512) {
            int m = m0 + i;
            s_tok[i] = (m < ne) ? g_slot_tok[e * CAP + m] : 0;
        }
        __syncthreads();
    }

    const float* rp[2];
    int arow[2], ac4[2], brow[2], bc4[2];
    #pragma unroll
    for (int i = 0; i < 2; i++) {
        int idx = tid + i * 512;
        arow[i] = idx >> 3; ac4[i] = idx & 7;
        rp[i] = EXPERT ? (X + (size_t)s_tok[arow[i]] * DDIM)
                       : (X + (size_t)(m0 + arow[i]) * DDIM);
        brow[i] = idx >> 5; bc4[i] = idx & 31;
    }

    const int lane = tid & 31, warp = tid >> 5;
    const int wm = (warp >> 2) * 32, wn = (warp & 3) * 32;
    const int g = lane >> 2, tig = lane & 3;

    float cG[2][4][4] = {};
    float cU[2][4][4] = {};

    const int NK = DDIM / 32;
    for (int kt = 0; kt < NK + 1; kt++) {
        if (kt < NK) {
            int b = kt & 1;
            float* sA  = bufs + b * 13312;
            float* sBg = sA + 4608;
            float* sBu = sBg + 4352;
            #pragma unroll
            for (int i = 0; i < 2; i++)
                cvt_store4(&sA[arow[i] * 36 + ac4[i] * 4], rp[i] + kt * 32 + ac4[i] * 4);
            #pragma unroll
            for (int i = 0; i < 2; i++) {
                size_t go = (size_t)(kt * 32 + brow[i]) * ldb + n0 + bc4[i] * 4;
                cvt_store4(&sBg[brow[i] * 136 + bc4[i] * 4], Bg + go);
                cvt_store4(&sBu[brow[i] * 136 + bc4[i] * 4], Bu + go);
            }
        }
        if (kt > 0) {
            int cur = (kt - 1) & 1;
            const uint32_t* uA  = (const uint32_t*)(bufs + cur * 13312);
            const uint32_t* uBg = uA + 4608;
            const uint32_t* uBu = uBg + 4352;
            #pragma unroll
            for (int ks = 0; ks < 4; ks++) {
                int ko = ks * 8;
                uint32_t a[2][4];
                #pragma unroll
                for (int mf = 0; mf < 2; mf++) {
                    int r = wm + mf * 16 + g;
                    a[mf][0] = uA[r * 36 + ko + tig];
                    a[mf][1] = uA[(r + 8) * 36 + ko + tig];
                    a[mf][2] = uA[r * 36 + ko + tig + 4];
                    a[mf][3] = uA[(r + 8) * 36 + ko + tig + 4];
                }
                #pragma unroll
                for (int nf = 0; nf < 4; nf++) {
                    int cn = wn + nf * 8 + g;
                    uint32_t bg0 = uBg[(ko + tig) * 136 + cn];
                    uint32_t bg1 = uBg[(ko + tig + 4) * 136 + cn];
                    mma8(cG[0][nf], a[0], bg0, bg1);
                    mma8(cG[1][nf], a[1], bg0, bg1);
                    uint32_t bu0 = uBu[(ko + tig) * 136 + cn];
                    uint32_t bu1 = uBu[(ko + tig + 4) * 136 + cn];
                    mma8(cU[0][nf], a[0], bu0, bu1);
                    mma8(cU[1][nf], a[1], bu0, bu1);
                }
            }
        }
        __syncthreads();
    }

    float* Hbase = EXPERT ? (g_H + (size_t)e * CAP * FDIM) : g_shared_h;
    #pragma unroll
    for (int mf = 0; mf < 2; mf++)
        #pragma unroll
        for (int nf = 0; nf < 4; nf++)
            #pragma unroll
            for (int i = 0; i < 4; i++) {
                int row = wm + mf * 16 + g + (i >> 1) * 8;
                int col = wn + nf * 8 + 2 * tig + (i & 1);
                int m = m0 + row;
                if (m < ne) {
                    float gg = cG[mf][nf][i], uu = cU[mf][nf][i];
                    float h = gg / (1.f + expf(-gg)) * uu;
                    Hbase[(size_t)m * FDIM + n0 + col] = h;
                }
            }
}

// -------------------- down GEMM --------------------
// K = FDIM = 768. per buffer floats: A 4608 + B 4352 = 8960
template<bool EXPERT>
__global__ __launch_bounds__(512)
void down_kernel(const float* __restrict__ WD, float* __restrict__ out) {
    extern __shared__ float smem[];
    float* bufs = smem;
    int* s_tok = (int*)(smem + 2 * 8960);
    float* s_w = (float*)(s_tok + 128);

    const int tid = threadIdx.x;
    const int e  = EXPERT ? blockIdx.z : 0;
    const int ne = EXPERT ? min(g_cnt[e], CAP) : T_TOK;
    const int m0 = blockIdx.y * 128;
    if (m0 >= ne) return;
    const int n0 = blockIdx.x * 128;

    const float* B = EXPERT ? (WD + (size_t)e * FDIM * DDIM) : WD;
    const float* Abase = EXPERT ? (g_H + (size_t)e * CAP * FDIM) : g_shared_h;

    if (EXPERT) {
        for (int i = tid; i < 128; i += 512) {
            int m = m0 + i;
            s_tok[i] = (m < ne) ? g_slot_tok[e * CAP + m] : 0;
            s_w[i]   = (m < ne) ? g_slot_w[e * CAP + m] : 0.f;
        }
        __syncthreads();
    }

    int arow[2], ac4[2], brow[2], bc4[2];
    #pragma unroll
    for (int i = 0; i < 2; i++) {
        int idx = tid + i * 512;
        arow[i] = idx >> 3; ac4[i] = idx & 7;
        brow[i] = idx >> 5; bc4[i] = idx & 31;
    }

    const int lane = tid & 31, warp = tid >> 5;
    const int wm = (warp >> 2) * 32, wn = (warp & 3) * 32;
    const int g = lane >> 2, tig = lane & 3;

    float c[2][4][4] = {};

    const int NK = FDIM / 32;
    for (int kt = 0; kt < NK + 1; kt++) {
        if (kt < NK) {
            int b = kt & 1;
            float* sA = bufs + b * 8960;
            float* sB = sA + 4608;
            #pragma unroll
            for (int i = 0; i < 2; i++)
                cvt_store4(&sA[arow[i] * 36 + ac4[i] * 4],
                           Abase + (size_t)(m0 + arow[i]) * FDIM + kt * 32 + ac4[i] * 4);
            #pragma unroll
            for (int i = 0; i < 2; i++)
                cvt_store4(&sB[brow[i] * 136 + bc4[i] * 4],
                           B + (size_t)(kt * 32 + brow[i]) * DDIM + n0 + bc4[i] * 4);
        }
        if (kt > 0) {
            int cur = (kt - 1) & 1;
            const uint32_t* uA = (const uint32_t*)(bufs + cur * 8960);
            const uint32_t* uB = uA + 4608;
            #pragma unroll
            for (int ks = 0; ks < 4; ks++) {
                int ko = ks * 8;
                uint32_t a[2][4];
                #pragma unroll
                for (int mf = 0; mf < 2; mf++) {
                    int r = wm + mf * 16 + g;
                    a[mf][0] = uA[r * 36 + ko + tig];
                    a[mf][1] = uA[(r + 8) * 36 + ko + tig];
                    a[mf][2] = uA[r * 36 + ko + tig + 4];
                    a[mf][3] = uA[(r + 8) * 36 + ko + tig + 4];
                }
                #pragma unroll
                for (int nf = 0; nf < 4; nf++) {
                    int cn = wn + nf * 8 + g;
                    uint32_t b0 = uB[(ko + tig) * 136 + cn];
                    uint32_t b1 = uB[(ko + tig + 4) * 136 + cn];
                    mma8(c[0][nf], a[0], b0, b1);
                    mma8(c[1][nf], a[1], b0, b1);
                }
            }
        }
        __syncthreads();
    }

    #pragma unroll
    for (int mf = 0; mf < 2; mf++)
        #pragma unroll
        for (int nf = 0; nf < 4; nf++)
            #pragma unroll
            for (int half = 0; half < 2; half++) {
                int row = wm + mf * 16 + g + half * 8;
                int col = wn + nf * 8 + 2 * tig;
                int m = m0 + row;
                if (m < ne) {
                    float v0 = c[mf][nf][half * 2];
                    float v1 = c[mf][nf][half * 2 + 1];
                    if (EXPERT) {
                        float w = s_w[row];
                        float* p = out + (size_t)s_tok[row] * DDIM + n0 + col;
                        asm volatile("red.global.add.v2.f32 [%0], {%1,%2};"
                                     :: "l"(p), "f"(v0 * w), "f"(v1 * w) : "memory");
                    } else {
                        float2* p = (float2*)(out + (size_t)m * DDIM + n0 + col);
                        *p = make_float2(v0, v1);
                    }
                }
            }
}

// -------------------- launch --------------------
extern "C" void kernel_launch(void* const* d_in, const int* in_sizes, int n_in,
                              void* d_out, int out_size) {
    const float* X   = (const float*)d_in[0];   // (B,S,D)
    const float* RW  = (const float*)d_in[1];   // (E,D)
    const float* WG  = (const float*)d_in[2];   // (E,D,F)
    const float* WU  = (const float*)d_in[3];   // (E,D,F)
    const float* WD  = (const float*)d_in[4];   // (E,F,D)
    const float* WSG = (const float*)d_in[5];   // (D, 2*SF)
    const float* WSD = (const float*)d_in[6];   // (SF, D)
    float* out = (float*)d_out;

    const int GUSM = (2 * 13312) * 4 + 128 * 4;        // 107008
    const int DSM  = (2 * 8960) * 4 + 128 * 8;         // 72704

    cudaFuncSetAttribute(gateup_kernel<false>, cudaFuncAttributeMaxDynamicSharedMemorySize, GUSM);
    cudaFuncSetAttribute(gateup_kernel<true>,  cudaFuncAttributeMaxDynamicSharedMemorySize, GUSM);
    cudaFuncSetAttribute(down_kernel<false>,   cudaFuncAttributeMaxDynamicSharedMemorySize, DSM);
    cudaFuncSetAttribute(down_kernel<true>,    cudaFuncAttributeMaxDynamicSharedMemorySize, DSM);

    zero_cnt_kernel<<<1, 64>>>();
    router_kernel<<<T_TOK / 32, 256>>>(X, RW);

    // shared expert gate/up: B = ws_gate_up, gate cols [0,768), up cols [768,1536)
    gateup_kernel<false><<<dim3(FDIM / 128, T_TOK / 128, 1), 512, GUSM>>>(X, WSG, WSG + FDIM, 2 * FDIM);
    // routed experts gate/up
    gateup_kernel<true><<<dim3(FDIM / 128, CAP / 128, NEXP), 512, GUSM>>>(X, WG, WU, FDIM);

    // shared expert down (initializes every element of out)
    down_kernel<false><<<dim3(DDIM / 128, T_TOK / 128, 1), 512, DSM>>>(WSD, out);
    // routed experts down (weighted atomic scatter)
    down_kernel<true><<<dim3(DDIM / 128, CAP / 128, NEXP), 512, DSM>>>(WD, out);
}

// round 8
// speedup vs baseline: 1.1755x; 1.1755x over previous
#include <cuda_runtime.h>
#include <cstdint>
#include <math.h>

#define T_TOK 2048
#define DDIM  1024
#define NEXP  64
#define TOPK  8
#define FDIM  768
#define CAP   512

// -------------------- device scratch --------------------
__device__ int   g_cnt[NEXP];
__device__ int   g_slot_tok[NEXP * CAP];
__device__ float g_slot_w[NEXP * CAP];
__device__ float g_H[(size_t)NEXP * CAP * FDIM];        // ~100.7 MB
__device__ float g_shared_h[(size_t)T_TOK * FDIM];      // ~6.3 MB

// -------------------- helpers --------------------
__device__ __forceinline__ uint32_t f2tf32(float x) {
    uint32_t r;
    asm("cvt.rna.tf32.f32 %0, %1;" : "=r"(r) : "f"(x));
    return r;
}

__device__ __forceinline__ void cvt_store4r(float* dst, float4 v) {
    uint4 o;
    o.x = f2tf32(v.x); o.y = f2tf32(v.y); o.z = f2tf32(v.z); o.w = f2tf32(v.w);
    *reinterpret_cast<uint4*>(dst) = o;
}

__device__ __forceinline__ void mma8(float c[4], const uint32_t a[4],
                                     uint32_t b0, uint32_t b1) {
    asm volatile(
        "mma.sync.aligned.m16n8k8.row.col.f32.tf32.tf32.f32 "
        "{%0,%1,%2,%3},{%4,%5,%6,%7},{%8,%9},{%0,%1,%2,%3};\n"
        : "+f"(c[0]), "+f"(c[1]), "+f"(c[2]), "+f"(c[3])
        : "r"(a[0]), "r"(a[1]), "r"(a[2]), "r"(a[3]), "r"(b0), "r"(b1));
}

// -------------------- counters reset --------------------
__global__ void zero_cnt_kernel() {
    if (threadIdx.x < NEXP) g_cnt[threadIdx.x] = 0;
}

// -------------------- router --------------------
__global__ __launch_bounds__(256)
void router_kernel(const float* __restrict__ X, const float* __restrict__ RW) {
    __shared__ float xs[32][68];
    __shared__ float rws[64][68];
    __shared__ float probs[32][65];

    const int tid = threadIdx.x;
    const int t0  = blockIdx.x * 32;
    const int t   = tid >> 3;
    const int el  = tid & 7;

    float acc[8] = {0.f,0.f,0.f,0.f,0.f,0.f,0.f,0.f};

    for (int kc = 0; kc < DDIM; kc += 64) {
        #pragma unroll
        for (int i = 0; i < 2; i++) {
            int idx = tid + i * 256;
            int row = idx >> 4, c4 = idx & 15;
            *reinterpret_cast<float4*>(&xs[row][c4 * 4]) =
                *reinterpret_cast<const float4*>(X + (size_t)(t0 + row) * DDIM + kc + c4 * 4);
        }
        #pragma unroll
        for (int i = 0; i < 4; i++) {
            int idx = tid + i * 256;
            int row = idx >> 4, c4 = idx & 15;
            *reinterpret_cast<float4*>(&rws[row][c4 * 4]) =
                *reinterpret_cast<const float4*>(RW + (size_t)row * DDIM + kc + c4 * 4);
        }
        __syncthreads();
        for (int k = 0; k < 64; k++) {
            float xv = xs[t][k];
            #pragma unroll
            for (int j = 0; j < 8; j++) acc[j] += xv * rws[el + 8 * j][k];
        }
        __syncthreads();
    }

    float mx = acc[0];
    #pragma unroll
    for (int j = 1; j < 8; j++) mx = fmaxf(mx, acc[j]);
    #pragma unroll
    for (int m = 1; m < 8; m <<= 1) mx = fmaxf(mx, __shfl_xor_sync(0xffffffffu, mx, m));
    float p[8], s = 0.f;
    #pragma unroll
    for (int j = 0; j < 8; j++) { p[j] = expf(acc[j] - mx); s += p[j]; }
    #pragma unroll
    for (int m = 1; m < 8; m <<= 1) s += __shfl_xor_sync(0xffffffffu, s, m);
    float inv = 1.f / s;
    #pragma unroll
    for (int j = 0; j < 8; j++) probs[t][el + 8 * j] = p[j] * inv;
    __syncthreads();

    if (tid < 32) {
        const int token = t0 + tid;
        float tw[TOPK]; int te[TOPK];
        float psum = 0.f;
        #pragma unroll
        for (int k = 0; k < TOPK; k++) {
            float best = -1.f; int be = 0;
            for (int e2 = 0; e2 < NEXP; e2++) {
                float v = probs[tid][e2];
                if (v > best) { best = v; be = e2; }
            }
            probs[tid][be] = -2.f;
            tw[k] = best; te[k] = be; psum += best;
        }
        float invp = 1.f / psum;
        #pragma unroll
        for (int k = 0; k < TOPK; k++) {
            int pos = atomicAdd(&g_cnt[te[k]], 1);
            if (pos < CAP) {
                g_slot_tok[te[k] * CAP + pos] = token;
                g_slot_w[te[k] * CAP + pos]   = tw[k] * invp;
            }
        }
    }
}

// -------------------- fused gate/up GEMM + SiLU --------------------
// BM=128, BN=128, BK=32, 512 threads (16 warps 4x4, 32x32 warp tile).
// Software-pipelined: LDG(kt+1) -> compute(kt) -> STS(kt+1) -> sync.
// per buffer floats: A 128*36=4608, Bg 32*136=4352, Bu 4352 => 13312
template<bool EXPERT>
__global__ __launch_bounds__(512)
void gateup_kernel(const float* __restrict__ X, const float* __restrict__ WG,
                   const float* __restrict__ WU, int ldb) {
    extern __shared__ float smem[];
    float* bufs = smem;
    int* s_tok = (int*)(smem + 2 * 13312);

    const int tid = threadIdx.x;
    const int e  = EXPERT ? blockIdx.z : 0;
    const int ne = EXPERT ? min(g_cnt[e], CAP) : T_TOK;
    const int m0 = blockIdx.y * 128;
    if (m0 >= ne) return;
    const int n0 = blockIdx.x * 128;

    const float* Bg = EXPERT ? (WG + (size_t)e * DDIM * FDIM) : WG;
    const float* Bu = EXPERT ? (WU + (size_t)e * DDIM * FDIM) : WU;

    if (EXPERT) {
        for (int i = tid; i < 128; i += 512) {
            int m = m0 + i;
            s_tok[i] = (m < ne) ? g_slot_tok[e * CAP + m] : 0;
        }
        __syncthreads();
    }

    const float* rp[2];
    int arow[2], ac4[2], brow[2], bc4[2];
    #pragma unroll
    for (int i = 0; i < 2; i++) {
        int idx = tid + i * 512;
        arow[i] = idx >> 3; ac4[i] = idx & 7;
        rp[i] = EXPERT ? (X + (size_t)s_tok[arow[i]] * DDIM)
                       : (X + (size_t)(m0 + arow[i]) * DDIM);
        brow[i] = idx >> 5; bc4[i] = idx & 31;
    }

    const int lane = tid & 31, warp = tid >> 5;
    const int wm = (warp >> 2) * 32, wn = (warp & 3) * 32;
    const int g = lane >> 2, tig = lane & 3;

    float cG[2][4][4] = {};
    float cU[2][4][4] = {};

    float4 hA[2], hBg[2], hBu[2];

    // prologue: load + store tile 0
    #pragma unroll
    for (int i = 0; i < 2; i++)
        hA[i] = *reinterpret_cast<const float4*>(rp[i] + ac4[i] * 4);
    #pragma unroll
    for (int i = 0; i < 2; i++) {
        size_t go = (size_t)brow[i] * ldb + n0 + bc4[i] * 4;
        hBg[i] = *reinterpret_cast<const float4*>(Bg + go);
        hBu[i] = *reinterpret_cast<const float4*>(Bu + go);
    }
    {
        float* sA  = bufs;
        float* sBg = sA + 4608;
        float* sBu = sBg + 4352;
        #pragma unroll
        for (int i = 0; i < 2; i++) {
            cvt_store4r(&sA[arow[i] * 36 + ac4[i] * 4], hA[i]);
            cvt_store4r(&sBg[brow[i] * 136 + bc4[i] * 4], hBg[i]);
            cvt_store4r(&sBu[brow[i] * 136 + bc4[i] * 4], hBu[i]);
        }
    }
    __syncthreads();

    const int NK = DDIM / 32;
    for (int kt = 0; kt < NK; kt++) {
        // issue global loads for tile kt+1 (latency hides under compute)
        if (kt + 1 < NK) {
            const int k1 = (kt + 1) * 32;
            #pragma unroll
            for (int i = 0; i < 2; i++)
                hA[i] = *reinterpret_cast<const float4*>(rp[i] + k1 + ac4[i] * 4);
            #pragma unroll
            for (int i = 0; i < 2; i++) {
                size_t go = (size_t)(k1 + brow[i]) * ldb + n0 + bc4[i] * 4;
                hBg[i] = *reinterpret_cast<const float4*>(Bg + go);
                hBu[i] = *reinterpret_cast<const float4*>(Bu + go);
            }
        }

        // compute tile kt
        {
            const uint32_t* uA  = (const uint32_t*)(bufs + (kt & 1) * 13312);
            const uint32_t* uBg = uA + 4608;
            const uint32_t* uBu = uBg + 4352;
            #pragma unroll
            for (int ks = 0; ks < 4; ks++) {
                int ko = ks * 8;
                uint32_t a[2][4];
                #pragma unroll
                for (int mf = 0; mf < 2; mf++) {
                    int r = wm + mf * 16 + g;
                    a[mf][0] = uA[r * 36 + ko + tig];
                    a[mf][1] = uA[(r + 8) * 36 + ko + tig];
                    a[mf][2] = uA[r * 36 + ko + tig + 4];
                    a[mf][3] = uA[(r + 8) * 36 + ko + tig + 4];
                }
                #pragma unroll
                for (int nf = 0; nf < 4; nf++) {
                    int cn = wn + nf * 8 + g;
                    uint32_t bg0 = uBg[(ko + tig) * 136 + cn];
                    uint32_t bg1 = uBg[(ko + tig + 4) * 136 + cn];
                    uint32_t bu0 = uBu[(ko + tig) * 136 + cn];
                    uint32_t bu1 = uBu[(ko + tig + 4) * 136 + cn];
                    mma8(cG[0][nf], a[0], bg0, bg1);
                    mma8(cG[1][nf], a[1], bg0, bg1);
                    mma8(cU[0][nf], a[0], bu0, bu1);
                    mma8(cU[1][nf], a[1], bu0, bu1);
                }
            }
        }

        // store tile kt+1 into the other buffer
        if (kt + 1 < NK) {
            float* sA  = bufs + ((kt + 1) & 1) * 13312;
            float* sBg = sA + 4608;
            float* sBu = sBg + 4352;
            #pragma unroll
            for (int i = 0; i < 2; i++) {
                cvt_store4r(&sA[arow[i] * 36 + ac4[i] * 4], hA[i]);
                cvt_store4r(&sBg[brow[i] * 136 + bc4[i] * 4], hBg[i]);
                cvt_store4r(&sBu[brow[i] * 136 + bc4[i] * 4], hBu[i]);
            }
        }
        __syncthreads();
    }

    float* Hbase = EXPERT ? (g_H + (size_t)e * CAP * FDIM) : g_shared_h;
    #pragma unroll
    for (int mf = 0; mf < 2; mf++)
        #pragma unroll
        for (int nf = 0; nf < 4; nf++)
            #pragma unroll
            for (int half = 0; half < 2; half++) {
                int row = wm + mf * 16 + g + half * 8;
                int col = wn + nf * 8 + 2 * tig;
                int m = m0 + row;
                if (m < ne) {
                    float g0 = cG[mf][nf][half * 2],     u0 = cU[mf][nf][half * 2];
                    float g1 = cG[mf][nf][half * 2 + 1], u1 = cU[mf][nf][half * 2 + 1];
                    float2 o;
                    o.x = g0 / (1.f + expf(-g0)) * u0;
                    o.y = g1 / (1.f + expf(-g1)) * u1;
                    *reinterpret_cast<float2*>(Hbase + (size_t)m * FDIM + n0 + col) = o;
                }
            }
}

// -------------------- down GEMM --------------------
// K = FDIM = 768. per buffer floats: A 4608 + B 4352 = 8960
template<bool EXPERT>
__global__ __launch_bounds__(512)
void down_kernel(const float* __restrict__ WD, float* __restrict__ out) {
    extern __shared__ float smem[];
    float* bufs = smem;
    int* s_tok = (int*)(smem + 2 * 8960);
    float* s_w = (float*)(s_tok + 128);

    const int tid = threadIdx.x;
    const int e  = EXPERT ? blockIdx.z : 0;
    const int ne = EXPERT ? min(g_cnt[e], CAP) : T_TOK;
    const int m0 = blockIdx.y * 128;
    if (m0 >= ne) return;
    const int n0 = blockIdx.x * 128;

    const float* B = EXPERT ? (WD + (size_t)e * FDIM * DDIM) : WD;
    const float* Abase = EXPERT ? (g_H + (size_t)e * CAP * FDIM) : g_shared_h;

    if (EXPERT) {
        for (int i = tid; i < 128; i += 512) {
            int m = m0 + i;
            s_tok[i] = (m < ne) ? g_slot_tok[e * CAP + m] : 0;
            s_w[i]   = (m < ne) ? g_slot_w[e * CAP + m] : 0.f;
        }
        __syncthreads();
    }

    int arow[2], ac4[2], brow[2], bc4[2];
    #pragma unroll
    for (int i = 0; i < 2; i++) {
        int idx = tid + i * 512;
        arow[i] = idx >> 3; ac4[i] = idx & 7;
        brow[i] = idx >> 5; bc4[i] = idx & 31;
    }

    const int lane = tid & 31, warp = tid >> 5;
    const int wm = (warp >> 2) * 32, wn = (warp & 3) * 32;
    const int g = lane >> 2, tig = lane & 3;

    float c[2][4][4] = {};
    float4 hA[2], hB[2];

    // prologue: tile 0
    #pragma unroll
    for (int i = 0; i < 2; i++) {
        hA[i] = *reinterpret_cast<const float4*>(Abase + (size_t)(m0 + arow[i]) * FDIM + ac4[i] * 4);
        hB[i] = *reinterpret_cast<const float4*>(B + (size_t)brow[i] * DDIM + n0 + bc4[i] * 4);
    }
    {
        float* sA = bufs;
        float* sB = sA + 4608;
        #pragma unroll
        for (int i = 0; i < 2; i++) {
            cvt_store4r(&sA[arow[i] * 36 + ac4[i] * 4], hA[i]);
            cvt_store4r(&sB[brow[i] * 136 + bc4[i] * 4], hB[i]);
        }
    }
    __syncthreads();

    const int NK = FDIM / 32;
    for (int kt = 0; kt < NK; kt++) {
        if (kt + 1 < NK) {
            const int k1 = (kt + 1) * 32;
            #pragma unroll
            for (int i = 0; i < 2; i++) {
                hA[i] = *reinterpret_cast<const float4*>(Abase + (size_t)(m0 + arow[i]) * FDIM + k1 + ac4[i] * 4);
                hB[i] = *reinterpret_cast<const float4*>(B + (size_t)(k1 + brow[i]) * DDIM + n0 + bc4[i] * 4);
            }
        }

        {
            const uint32_t* uA = (const uint32_t*)(bufs + (kt & 1) * 8960);
            const uint32_t* uB = uA + 4608;
            #pragma unroll
            for (int ks = 0; ks < 4; ks++) {
                int ko = ks * 8;
                uint32_t a[2][4];
                #pragma unroll
                for (int mf = 0; mf < 2; mf++) {
                    int r = wm + mf * 16 + g;
                    a[mf][0] = uA[r * 36 + ko + tig];
                    a[mf][1] = uA[(r + 8) * 36 + ko + tig];
                    a[mf][2] = uA[r * 36 + ko + tig + 4];
                    a[mf][3] = uA[(r + 8) * 36 + ko + tig + 4];
                }
                #pragma unroll
                for (int nf = 0; nf < 4; nf++) {
                    int cn = wn + nf * 8 + g;
                    uint32_t b0 = uB[(ko + tig) * 136 + cn];
                    uint32_t b1 = uB[(ko + tig + 4) * 136 + cn];
                    mma8(c[0][nf], a[0], b0, b1);
                    mma8(c[1][nf], a[1], b0, b1);
                }
            }
        }

        if (kt + 1 < NK) {
            float* sA = bufs + ((kt + 1) & 1) * 8960;
            float* sB = sA + 4608;
            #pragma unroll
            for (int i = 0; i < 2; i++) {
                cvt_store4r(&sA[arow[i] * 36 + ac4[i] * 4], hA[i]);
                cvt_store4r(&sB[brow[i] * 136 + bc4[i] * 4], hB[i]);
            }
        }
        __syncthreads();
    }

    #pragma unroll
    for (int mf = 0; mf < 2; mf++)
        #pragma unroll
        for (int nf = 0; nf < 4; nf++)
            #pragma unroll
            for (int half = 0; half < 2; half++) {
                int row = wm + mf * 16 + g + half * 8;
                int col = wn + nf * 8 + 2 * tig;
                int m = m0 + row;
                if (m < ne) {
                    float v0 = c[mf][nf][half * 2];
                    float v1 = c[mf][nf][half * 2 + 1];
                    if (EXPERT) {
                        float w = s_w[row];
                        float* p = out + (size_t)s_tok[row] * DDIM + n0 + col;
                        asm volatile("red.global.add.v2.f32 [%0], {%1,%2};"
                                     :: "l"(p), "f"(v0 * w), "f"(v1 * w) : "memory");
                    } else {
                        float2* p = (float2*)(out + (size_t)m * DDIM + n0 + col);
                        *p = make_float2(v0, v1);
                    }
                }
            }
}

// -------------------- launch --------------------
extern "C" void kernel_launch(void* const* d_in, const int* in_sizes, int n_in,
                              void* d_out, int out_size) {
    const float* X   = (const float*)d_in[0];   // (B,S,D)
    const float* RW  = (const float*)d_in[1];   // (E,D)
    const float* WG  = (const float*)d_in[2];   // (E,D,F)
    const float* WU  = (const float*)d_in[3];   // (E,D,F)
    const float* WD  = (const float*)d_in[4];   // (E,F,D)
    const float* WSG = (const float*)d_in[5];   // (D, 2*SF)
    const float* WSD = (const float*)d_in[6];   // (SF, D)
    float* out = (float*)d_out;

    const int GUSM = (2 * 13312) * 4 + 128 * 4;        // 107008
    const int DSM  = (2 * 8960) * 4 + 128 * 8;         // 72704

    cudaFuncSetAttribute(gateup_kernel<false>, cudaFuncAttributeMaxDynamicSharedMemorySize, GUSM);
    cudaFuncSetAttribute(gateup_kernel<true>,  cudaFuncAttributeMaxDynamicSharedMemorySize, GUSM);
    cudaFuncSetAttribute(down_kernel<false>,   cudaFuncAttributeMaxDynamicSharedMemorySize, DSM);
    cudaFuncSetAttribute(down_kernel<true>,    cudaFuncAttributeMaxDynamicSharedMemorySize, DSM);

    zero_cnt_kernel<<<1, 64>>>();
    router_kernel<<<T_TOK / 32, 256>>>(X, RW);

    // shared expert gate/up: gate cols [0,768), up cols [768,1536)
    gateup_kernel<false><<<dim3(FDIM / 128, T_TOK / 128, 1), 512, GUSM>>>(X, WSG, WSG + FDIM, 2 * FDIM);
    // routed experts gate/up
    gateup_kernel<true><<<dim3(FDIM / 128, CAP / 128, NEXP), 512, GUSM>>>(X, WG, WU, FDIM);

    // shared expert down (initializes every element of out)
    down_kernel<false><<<dim3(DDIM / 128, T_TOK / 128, 1), 512, DSM>>>(WSD, out);
    // routed experts down (weighted atomic scatter)
    down_kernel<true><<<dim3(DDIM / 128, CAP / 128, NEXP), 512, DSM>>>(WD, out);
}